// round 12
// baseline (speedup 1.0000x reference)
#include <cuda_runtime.h>
#include <cuda_bf16.h>
#include <math.h>
#include <stdint.h>

// Problem constants
#define NN   512
#define LL   64
#define DH   256
#define DX   64
#define QQ   8192
#define NTYP 16
#define NMEM 262144
#define NSEG (NN*LL)        // 32768

// Scratch (device globals; no allocation allowed)
__device__ __align__(16) float g_xsum[NSEG * DX];       // 8 MB
__device__ __align__(16) float g_wv  [QQ * DH];         // 8 MB
__device__ __align__(16) float g_w2  [2 * DH * DH];     // 512x256
__device__ __align__(16) float g_y   [NSEG * NTYP];     // 2 MB
__device__ __align__(16) float g_l0  [QQ * NTYP];       // 512 KB
__device__ float g_b2  [DH];
__device__ int   g_em  [NN];
__device__ int   g_acc_cnt;

// ---------------------------------------------------------------------------
// Kernel 1: x_sum = segment_sum(tok_emb[mem], grp)  (MLP=4, v4 red)
// ---------------------------------------------------------------------------
#define SC_NT (NMEM * 16 / 4)   // 1,048,576 threads
__global__ __launch_bounds__(256)
void scatter_kernel(const float* __restrict__ tok_emb,
                    const int*   __restrict__ mem,
                    const int*   __restrict__ grp) {
    int t = blockIdx.x * 256 + threadIdx.x;
    int   gg[4], qd[4];
    float4 v[4];
    #pragma unroll
    for (int k = 0; k < 4; k++) {
        int task = t + k * SC_NT;
        int e = task >> 4;
        qd[k] = task & 15;
        int tok = __ldg(&mem[e]);
        gg[k]  = __ldg(&grp[e]);
        v[k] = __ldg(reinterpret_cast<const float4*>(tok_emb) + tok * 16 + qd[k]);
    }
    #pragma unroll
    for (int k = 0; k < 4; k++) {
        float* dst = &g_xsum[(size_t)gg[k] * DX + qd[k] * 4];
        asm volatile("red.global.add.v4.f32 [%0], {%1, %2, %3, %4};"
                     :: "l"(dst), "f"(v[k].x), "f"(v[k].y), "f"(v[k].z), "f"(v[k].w)
                     : "memory");
    }
}

// ---------------------------------------------------------------------------
// Kernel 2 (prep): grid 225 blocks, 256 threads. All fp32 paths.
//   bx 0..31   : W2 tile ; bx == 32 : b2 + init
//   bx 33..96  : l0 tile (BM=128, N=16) ; bx 97..224 : y rows
// ---------------------------------------------------------------------------
#define L0_AS  132   // [32][132]
#define L0_BS  17    // [32][17]
__global__ __launch_bounds__(256)
void prep_kernel(const float* __restrict__ Wq, const float* __restrict__ Wk,
                 const float* __restrict__ bq, const float* __restrict__ Wrel,
                 const float* __restrict__ h_grp,
                 const int* __restrict__ idx,
                 const int* __restrict__ src,
                 const int* __restrict__ dst) {
    __shared__ float sma[32 * L0_AS + 32 * L0_BS];   // 19 KB
    __shared__ int   sOff[2 * 128];
    const int tid = threadIdx.x;
    const int bx  = blockIdx.x;

    if (bx < 32) {
        float* s_wq = sma;              // [256][16]
        int k0 = bx * 16;
        #pragma unroll
        for (int r = 0; r < 16; r++) {
            int fid = tid + r * 256;
            int d = fid >> 4, kl = fid & 15;
            s_wq[d * 16 + kl] = __ldg(&Wq[(size_t)d * (2 * DH) + k0 + kl]);
        }
        __syncthreads();
        float acc[16] = {};
        int e = tid;
        #pragma unroll 4
        for (int d = 0; d < DH; d++) {
            float wkv = __ldg(&Wk[(size_t)d * DH + e]);
            #pragma unroll
            for (int kl = 0; kl < 16; kl++) acc[kl] += s_wq[d * 16 + kl] * wkv;
        }
        #pragma unroll
        for (int kl = 0; kl < 16; kl++)
            g_w2[(size_t)(k0 + kl) * DH + e] = acc[kl];
        return;
    }
    if (bx == 32) {
        float b2 = 0.f;
        for (int d = 0; d < DH; d++)
            b2 += __ldg(&bq[d]) * __ldg(&Wk[(size_t)d * DH + tid]);
        g_b2[tid] = b2;
        g_em[tid] = 0x7fffffff;
        g_em[tid + 256] = 0x7fffffff;
        if (tid == 0) g_acc_cnt = 0;
        return;
    }
    if (bx >= 97) {
        float* wx = sma;   // [16][65]
        #pragma unroll
        for (int r = 0; r < 4; r++) {
            int v = tid + r * 256;
            int t = v >> 6, j = v & 63;
            wx[t * 65 + j] = __ldg(&Wrel[(size_t)t * (2 * DH + DX) + 2 * DH + j]);
        }
        __syncthreads();
        int row = (bx - 97) * 256 + tid;
        const float4* x4 = reinterpret_cast<const float4*>(g_xsum + (size_t)row * DX);
        float acc[NTYP] = {};
        #pragma unroll
        for (int j4 = 0; j4 < 16; j4++) {
            float4 x = x4[j4];
            int j = j4 * 4;
            #pragma unroll
            for (int t = 0; t < NTYP; t++)
                acc[t] += x.x * wx[t * 65 + j]     + x.y * wx[t * 65 + j + 1]
                        + x.z * wx[t * 65 + j + 2] + x.w * wx[t * 65 + j + 3];
        }
        float4* yo = reinterpret_cast<float4*>(g_y + (size_t)row * NTYP);
        #pragma unroll
        for (int t4 = 0; t4 < 4; t4++)
            yo[t4] = make_float4(acc[t4 * 4], acc[t4 * 4 + 1], acc[t4 * 4 + 2], acc[t4 * 4 + 3]);
        return;
    }

    // ---- l0 tile: BM=128, N=16 ----
    float* As = sma;                 // [32][L0_AS]
    float* Bs = sma + 32 * L0_AS;    // [32][L0_BS]
    const int row0 = (bx - 33) * 128;

    if (tid < 128) {
        int q = row0 + tid;
        int i = __ldg(&idx[q]);
        sOff[tid]       = (i * LL + __ldg(&src[q])) * DH;
        sOff[128 + tid] = (i * LL + __ldg(&dst[q])) * DH;
    }
    __syncthreads();

    const int ty = tid >> 4;
    const int tx = tid & 15;
    float acc[8] = {};
    const int amr = tid >> 3;
    const int ac4 = (tid & 7) * 4;

    for (int ch = 0; ch < 16; ch++) {
        int kb = ch * 32;
        const int* off = sOff + ((kb >> 8) << 7);
        int kbl = kb & 255;
        float4 rA[4];
        #pragma unroll
        for (int j = 0; j < 4; j++)
            rA[j] = *reinterpret_cast<const float4*>(h_grp + off[amr + 32 * j] + kbl + ac4);
        float rb0 = __ldg(&Wrel[(size_t)(tid & 15) * (2 * DH + DX) + kb + (tid >> 4)]);
        float rb1 = __ldg(&Wrel[(size_t)(tid & 15) * (2 * DH + DX) + kb + (tid >> 4) + 16]);
        __syncthreads();
        #pragma unroll
        for (int j = 0; j < 4; j++) {
            int r = amr + 32 * j;
            As[(ac4 + 0) * L0_AS + r] = rA[j].x;
            As[(ac4 + 1) * L0_AS + r] = rA[j].y;
            As[(ac4 + 2) * L0_AS + r] = rA[j].z;
            As[(ac4 + 3) * L0_AS + r] = rA[j].w;
        }
        Bs[(tid >> 4) * L0_BS + (tid & 15)]        = rb0;
        Bs[((tid >> 4) + 16) * L0_BS + (tid & 15)] = rb1;
        __syncthreads();

        #pragma unroll
        for (int k = 0; k < 32; k++) {
            float b = Bs[k * L0_BS + tx];
            const float* ar = As + k * L0_AS + ty * 8;
            #pragma unroll
            for (int i = 0; i < 8; i++) acc[i] += ar[i] * b;
        }
    }
    #pragma unroll
    for (int i = 0; i < 8; i++) {
        int q = row0 + ty * 8 + i;
        g_l0[(size_t)q * NTYP + tx] = acc[i];
    }
}

// ---------------------------------------------------------------------------
// Kernel 3: TF32 gather-GEMM via cp.async: wv = q_in @ W2 + b2
// BM=64, BN=128, BK=32, 256 threads (warps 2Mx4N), grid (2,128).
// ---------------------------------------------------------------------------
#define AS_STRIDE 36
#define BS_STRIDE 136
#define GEMM_SMEM_FLOATS (2 * 64 * AS_STRIDE + 2 * 32 * BS_STRIDE + 128)
#define GEMM_SMEM_BYTES  (GEMM_SMEM_FLOATS * 4)

#define CP16(dst_u32, src_ptr) \
    asm volatile("cp.async.ca.shared.global [%0], [%1], 16;" :: "r"(dst_u32), "l"(src_ptr))
#define CP_COMMIT() asm volatile("cp.async.commit_group;")
#define CP_WAIT0()  asm volatile("cp.async.wait_group 0;")

__device__ __forceinline__ void mma_tf32(float* c, const uint32_t* a, const uint32_t* b) {
    asm volatile(
        "mma.sync.aligned.m16n8k8.row.col.f32.tf32.tf32.f32 "
        "{%0,%1,%2,%3}, {%4,%5,%6,%7}, {%8,%9}, {%0,%1,%2,%3};"
        : "+f"(c[0]), "+f"(c[1]), "+f"(c[2]), "+f"(c[3])
        : "r"(a[0]), "r"(a[1]), "r"(a[2]), "r"(a[3]), "r"(b[0]), "r"(b[1]));
}

__global__ __launch_bounds__(256, 3)
void gemm_tf32(const float* __restrict__ h_grp,
               const int* __restrict__ idx,
               const int* __restrict__ src,
               const int* __restrict__ dst) {
    extern __shared__ float dsm[];
    float* As = dsm;                                  // [2][64][AS_STRIDE]
    float* Bs = dsm + 2 * 64 * AS_STRIDE;             // [2][32][BS_STRIDE]
    int*  sOff = (int*)(Bs + 2 * 32 * BS_STRIDE);     // [2][64]

    const int tid  = threadIdx.x;
    const int lane = tid & 31;
    const int w    = tid >> 5;
    const int wm   = (w & 1) * 32;
    const int wn   = (w >> 1) * 32;
    const int row0 = blockIdx.y * 64;
    const int col0 = blockIdx.x * 128;

    if (tid < 64) {
        int q = row0 + tid;
        int i = __ldg(&idx[q]);
        sOff[tid]      = (i * LL + __ldg(&src[q])) * DH;
        sOff[64 + tid] = (i * LL + __ldg(&dst[q])) * DH;
    }
    __syncthreads();

    const int amr = tid >> 3;
    const int ac4 = (tid & 7) * 4;
    const int bkr = tid >> 5;
    const int bn4 = (tid & 31) * 4;

    int oA[2][2];
    oA[0][0] = sOff[amr];      oA[0][1] = sOff[amr + 32];
    oA[1][0] = sOff[64 + amr]; oA[1][1] = sOff[64 + amr + 32];

    const uint32_t as_u = (uint32_t)__cvta_generic_to_shared(As);
    const uint32_t bs_u = (uint32_t)__cvta_generic_to_shared(Bs);
    const uint32_t aDst = as_u + (uint32_t)((amr * AS_STRIDE + ac4) * 4);
    const uint32_t aDst2 = as_u + (uint32_t)(((amr + 32) * AS_STRIDE + ac4) * 4);
    const uint32_t bDst = bs_u + (uint32_t)((bkr * BS_STRIDE + bn4) * 4);

    auto cpChunk = [&](int ch) {
        int buf = ch & 1;
        int kb = ch * 32, kbl = kb & 255, h = kb >> 8;
        uint32_t ab = (uint32_t)(buf * (64 * AS_STRIDE * 4));
        CP16(aDst + ab,  h_grp + oA[h][0] + kbl + ac4);
        CP16(aDst2 + ab, h_grp + oA[h][1] + kbl + ac4);
        uint32_t bb = (uint32_t)(buf * (32 * BS_STRIDE * 4));
        #pragma unroll
        for (int j = 0; j < 4; j++)
            CP16(bDst + bb + (uint32_t)(8 * j * BS_STRIDE * 4),
                 g_w2 + (size_t)(kb + bkr + 8 * j) * DH + col0 + bn4);
        CP_COMMIT();
    };

    float acc[2][4][4] = {};
    cpChunk(0);
    CP_WAIT0();
    __syncthreads();

    for (int t = 0; t < 16; t++) {
        if (t < 15) cpChunk(t + 1);
        const int buf = t & 1;
        const float* a = As + buf * 64 * AS_STRIDE;
        const float* b = Bs + buf * 32 * BS_STRIDE;
        const int ar = wm + (lane >> 2);
        const int bn = wn + (lane >> 2);
        #pragma unroll
        for (int ks = 0; ks < 4; ks++) {
            int kc = ks * 8 + (lane & 3);
            uint32_t af[2][4], bf[4][2];
            #pragma unroll
            for (int mt = 0; mt < 2; mt++) {
                const float* ap = a + (ar + mt * 16) * AS_STRIDE + kc;
                af[mt][0] = __float_as_uint(ap[0]);
                af[mt][1] = __float_as_uint(ap[8 * AS_STRIDE]);
                af[mt][2] = __float_as_uint(ap[4]);
                af[mt][3] = __float_as_uint(ap[8 * AS_STRIDE + 4]);
            }
            #pragma unroll
            for (int nt = 0; nt < 4; nt++) {
                const float* bp = b + kc * BS_STRIDE + bn + nt * 8;
                bf[nt][0] = __float_as_uint(bp[0]);
                bf[nt][1] = __float_as_uint(bp[4 * BS_STRIDE]);
            }
            #pragma unroll
            for (int mt = 0; mt < 2; mt++)
                #pragma unroll
                for (int nt = 0; nt < 4; nt++)
                    mma_tf32(acc[mt][nt], af[mt], bf[nt]);
        }
        if (t < 15) {
            CP_WAIT0();
            __syncthreads();
        }
    }

    #pragma unroll
    for (int mt = 0; mt < 2; mt++) {
        int r = row0 + wm + mt * 16 + (lane >> 2);
        #pragma unroll
        for (int nt = 0; nt < 4; nt++) {
            int cb = col0 + wn + nt * 8 + (lane & 3) * 2;
            float b0 = __ldg(&g_b2[cb]);
            float b1 = __ldg(&g_b2[cb + 1]);
            *reinterpret_cast<float2*>(&g_wv[(size_t)r * DH + cb]) =
                make_float2(acc[mt][nt][0] + b0, acc[mt][nt][1] + b1);
            *reinterpret_cast<float2*>(&g_wv[(size_t)(r + 8) * DH + cb]) =
                make_float2(acc[mt][nt][2] + b0, acc[mt][nt][3] + b1);
        }
    }
}

// ---------------------------------------------------------------------------
// Kernel 4 (ncu slot): block-per-group attention, 512 threads / 16 warps,
// ONE query per warp. wv and softmax weights live in registers (+shfl);
// smem 68.6 KB -> 3 blocks/SM = 48 warps (75% occ).
// First pass's wv/l0/typ prefetched before the staging barrier.
// ---------------------------------------------------------------------------
__device__ __forceinline__ int lbound(const int* __restrict__ a, int n, int key) {
    int lo = 0, hi = n;
    while (lo < hi) { int m = (lo + hi) >> 1; if (__ldg(&a[m]) < key) lo = m + 1; else hi = m; }
    return lo;
}

#define ATTN_WARPS 16
#define ATTN_SMEM_FLOATS (16384 + 1024 + 64 + 64 + 32)
#define ATTN_SMEM_BYTES  (ATTN_SMEM_FLOATS * 4)

__global__ __launch_bounds__(512, 3)
void attn_kernel(const float* __restrict__ h_grp,
                 const float* __restrict__ brel,
                 const int*   __restrict__ idx,
                 const int*   __restrict__ pos2grp,
                 const int*   __restrict__ msk,
                 const int*   __restrict__ typ,
                 float* __restrict__ out_logit) {
    extern __shared__ float sm[];
    float* s_ht  = sm;                          // 16384 : transposed h, [e][l]
    float* s_y   = s_ht  + 16384;               // 1024  : y [l][16]
    float* s_msk = s_y   + 1024;                // 64
    int*   s_g   = (int*)(s_msk + 64);          // 64
    int*   s_acc = s_g + 64;                    // 16
    int*   s_em  = s_acc + 16;                  // 16

    const int n    = blockIdx.x;
    const int tid  = threadIdx.x;     // 512
    const int lane = tid & 31;
    const int w    = tid >> 5;        // 16 warps

    const int lo = lbound(idx, QQ, n);
    const int hi = lbound(idx, QQ, n + 1);
    if (lo >= hi) return;

    const int tt = lane & 15;

    // ---- prefetch first pass's wv/l0/typ (hidden behind staging) ----
    int q = lo + w;
    float wvreg[8];
    float l0v = 0.f;
    int   tyv = 0;
    if (q < hi) {
        const float* wvr = g_wv + (size_t)q * DH;
        #pragma unroll
        for (int k = 0; k < 8; k++) wvreg[k] = __ldg(wvr + k * 32 + lane);
        l0v = __ldg(&g_l0[(size_t)q * NTYP + tt]);
        tyv = __ldg(&typ[q * NTYP + tt]);
    }

    // ---- stage h transposed (conflict-free STS), 512 threads ----
    {
        const float4* hb4 = reinterpret_cast<const float4*>(h_grp + (size_t)n * LL * DH);
        #pragma unroll
        for (int k = 0; k < 8; k++) {
            int v = tid + k * 512;
            int l = v & 63, e4 = v >> 6;
            float4 hv = __ldg(hb4 + l * 64 + e4);
            int e = e4 * 4;
            s_ht[(e + 0) * 64 + l] = hv.x;
            s_ht[(e + 1) * 64 + l] = hv.y;
            s_ht[(e + 2) * 64 + l] = hv.z;
            s_ht[(e + 3) * 64 + l] = hv.w;
        }
    }
    if (tid < LL) {
        s_g[tid]   = __ldg(&pos2grp[n * LL + tid]);
        s_msk[tid] = (__ldg(&msk[n * LL + tid]) == 0) ? -INFINITY : 0.f;
    }
    __syncthreads();

    // gather y rows (64 x 16)
    #pragma unroll
    for (int k = 0; k < 2; k++) {
        int v = tid + k * 512;
        int l = v >> 4, t = v & 15;
        s_y[l * 16 + t] = __ldg(&g_y[(size_t)s_g[l] * NTYP + t]);
    }
    __syncthreads();

    int accW = 0, emW = 1;
    const float2* ht2 = reinterpret_cast<const float2*>(s_ht);
    const float mk0 = s_msk[2 * lane];
    const float mk1 = s_msk[2 * lane + 1];
    const float brl = __ldg(&brel[tt]);

    while (q < hi) {
        // ---- scores for rows 2*lane, 2*lane+1 (wv broadcast via shfl) ----
        float p0a = 0.f, p0b = 0.f, p1a = 0.f, p1b = 0.f;
        #pragma unroll
        for (int k = 0; k < 8; k++) {
            float wk = wvreg[k];
            #pragma unroll 8
            for (int e2 = 0; e2 < 32; e2++) {
                float we = __shfl_sync(0xffffffffu, wk, e2);
                float2 h = ht2[(k * 32 + e2) * 32 + lane];
                if (e2 & 1) { p0b += h.x * we; p1b += h.y * we; }
                else        { p0a += h.x * we; p1a += h.y * we; }
            }
        }
        float v0 = (p0a + p0b) * 0.0625f + mk0;
        float v1 = (p1a + p1b) * 0.0625f + mk1;

        // ---- warp softmax over 64 ----
        float mmx = fmaxf(v0, v1);
        #pragma unroll
        for (int o = 16; o > 0; o >>= 1) mmx = fmaxf(mmx, __shfl_xor_sync(0xffffffffu, mmx, o));
        float e0 = __expf(v0 - mmx), e1 = __expf(v1 - mmx);
        float ssum = e0 + e1;
        #pragma unroll
        for (int o = 16; o > 0; o >>= 1) ssum += __shfl_xor_sync(0xffffffffu, ssum, o);
        float inv = 1.f / ssum;
        float a0 = e0 * inv, a1 = e1 * inv;   // rows 2*lane, 2*lane+1

        // ---- logit: a broadcast via shfl; lanes 0-15 & 16-31 duplicate ----
        float pa = 0.f, pb = 0.f;
        #pragma unroll
        for (int l = 0; l < LL; l += 2) {
            float av0 = __shfl_sync(0xffffffffu, a0, l >> 1);
            float av1 = __shfl_sync(0xffffffffu, a1, l >> 1);
            pa += av0 * s_y[l * 16 + tt];
            pb += av1 * s_y[(l + 1) * 16 + tt];
        }
        float logit = pa + pb + l0v + brl;
        if (lane < 16) out_logit[(size_t)q * NTYP + tt] = logit;

        int gt = (logit > 0.f) ? 1 : 0;
        int ty = (tyv > 0) ? 1 : 0;
        unsigned m = __ballot_sync(0xffffffffu, gt == ty) & 0xFFFFu;
        if (lane == 0) {
            accW += __popc(m);
            emW &= (m == 0xFFFFu) ? 1 : 0;
        }

        // ---- next pass (rare; avg 1 pass/warp) ----
        q += ATTN_WARPS;
        if (q < hi) {
            const float* wvr = g_wv + (size_t)q * DH;
            #pragma unroll
            for (int k = 0; k < 8; k++) wvreg[k] = __ldg(wvr + k * 32 + lane);
            l0v = __ldg(&g_l0[(size_t)q * NTYP + tt]);
            tyv = __ldg(&typ[q * NTYP + tt]);
        }
    }

    if (lane == 0) { s_acc[w] = accW; s_em[w] = emW; }
    __syncthreads();
    if (tid == 0) {
        int a = 0, e = 1;
        #pragma unroll
        for (int r = 0; r < ATTN_WARPS; r++) { a += s_acc[r]; e &= s_em[r]; }
        atomicAdd(&g_acc_cnt, a);
        g_em[n] = e;
    }
}

// ---------------------------------------------------------------------------
// Kernel 5: finalize. out layout: [logit(131072), acc, emr, em(512)]
// ---------------------------------------------------------------------------
__global__ __launch_bounds__(512)
void finalize_kernel(float* __restrict__ out) {
    __shared__ float s_red[16];
    int tid = threadIdx.x;
    int lane = tid & 31, w = tid >> 5;
    float e = (float)g_em[tid];
    out[QQ * NTYP + 2 + tid] = e;
    float p = e;
    #pragma unroll
    for (int o = 16; o > 0; o >>= 1) p += __shfl_xor_sync(0xffffffffu, p, o);
    if (lane == 0) s_red[w] = p;
    __syncthreads();
    if (tid == 0) {
        float sum = 0.f;
        #pragma unroll
        for (int r = 0; r < 16; r++) sum += s_red[r];
        out[QQ * NTYP + 0] = (float)g_acc_cnt / (float)(QQ * NTYP);
        out[QQ * NTYP + 1] = sum / (float)NN;
    }
}

// ---------------------------------------------------------------------------
extern "C" void kernel_launch(void* const* d_in, const int* in_sizes, int n_in,
                              void* d_out, int out_size) {
    const float* h_grp   = (const float*)d_in[0];
    const float* tok_emb = (const float*)d_in[1];
    const float* Wq      = (const float*)d_in[2];
    const float* bq      = (const float*)d_in[3];
    const float* Wk      = (const float*)d_in[4];
    const float* Wrel    = (const float*)d_in[6];
    const float* brel    = (const float*)d_in[7];
    const int*   mem     = (const int*)d_in[8];
    const int*   grp     = (const int*)d_in[9];
    const int*   pos2grp = (const int*)d_in[10];
    const int*   msk     = (const int*)d_in[11];
    const int*   idx     = (const int*)d_in[12];
    const int*   src     = (const int*)d_in[13];
    const int*   dst     = (const int*)d_in[14];
    const int*   typ     = (const int*)d_in[15];
    float* out = (float*)d_out;

    float* xsum_ptr; cudaGetSymbolAddress((void**)&xsum_ptr, g_xsum);

    // memset node (not a kernel launch)
    cudaMemsetAsync(xsum_ptr, 0, (size_t)NSEG * DX * sizeof(float));

    // kernel #1: segment-sum scatter
    scatter_kernel<<<SC_NT / 256, 256>>>(tok_emb, mem, grp);

    // kernel #2: prep (W2 + b2/init + l0 + y)
    prep_kernel<<<225, 256>>>(Wq, Wk, bq, Wrel, h_grp, idx, src, dst);

    // kernel #3: TF32 gather-GEMM wv (cp.async pipeline)
    {
        cudaFuncSetAttribute(gemm_tf32, cudaFuncAttributeMaxDynamicSharedMemorySize, GEMM_SMEM_BYTES);
        dim3 grid(DH / 128, QQ / 64);
        gemm_tf32<<<grid, 256, GEMM_SMEM_BYTES>>>(h_grp, idx, src, dst);
    }

    // kernel #4 (ncu slot): attention + logits + metrics (512 threads, 1 q/warp)
    cudaFuncSetAttribute(attn_kernel, cudaFuncAttributeMaxDynamicSharedMemorySize, ATTN_SMEM_BYTES);
    attn_kernel<<<NN, 512, ATTN_SMEM_BYTES>>>(h_grp, brel, idx, pos2grp, msk, typ, out);

    // kernel #5: finalize
    finalize_kernel<<<1, 512>>>(out);
}

// round 13
// speedup vs baseline: 1.0686x; 1.0686x over previous
#include <cuda_runtime.h>
#include <cuda_bf16.h>
#include <math.h>
#include <stdint.h>

// Problem constants
#define NN   512
#define LL   64
#define DH   256
#define DX   64
#define QQ   8192
#define NTYP 16
#define NMEM 262144
#define NSEG (NN*LL)        // 32768

// Scratch (device globals; no allocation allowed)
__device__ __align__(16) float g_xsum[NSEG * DX];       // 8 MB
__device__ __align__(16) float g_wv  [QQ * DH];         // 8 MB
__device__ __align__(16) float g_w2  [2 * DH * DH];     // 512x256
__device__ __align__(16) float g_y   [NSEG * NTYP];     // 2 MB
__device__ __align__(16) float g_l0  [QQ * NTYP];       // 512 KB
__device__ float g_b2  [DH];
__device__ int   g_em  [NN];
__device__ int   g_acc_cnt;

// ---------------------------------------------------------------------------
// Kernel 1: x_sum = segment_sum(tok_emb[mem], grp)  (MLP=4, v4 red)
// ---------------------------------------------------------------------------
#define SC_NT (NMEM * 16 / 4)   // 1,048,576 threads
__global__ __launch_bounds__(256)
void scatter_kernel(const float* __restrict__ tok_emb,
                    const int*   __restrict__ mem,
                    const int*   __restrict__ grp) {
    int t = blockIdx.x * 256 + threadIdx.x;
    int   gg[4], qd[4];
    float4 v[4];
    #pragma unroll
    for (int k = 0; k < 4; k++) {
        int task = t + k * SC_NT;
        int e = task >> 4;
        qd[k] = task & 15;
        int tok = __ldg(&mem[e]);
        gg[k]  = __ldg(&grp[e]);
        v[k] = __ldg(reinterpret_cast<const float4*>(tok_emb) + tok * 16 + qd[k]);
    }
    #pragma unroll
    for (int k = 0; k < 4; k++) {
        float* dst = &g_xsum[(size_t)gg[k] * DX + qd[k] * 4];
        asm volatile("red.global.add.v4.f32 [%0], {%1, %2, %3, %4};"
                     :: "l"(dst), "f"(v[k].x), "f"(v[k].y), "f"(v[k].z), "f"(v[k].w)
                     : "memory");
    }
}

// ---------------------------------------------------------------------------
// Kernel 2 (prep): grid 225 blocks, 256 threads. All fp32 paths.
//   bx 0..31   : W2 tile ; bx == 32 : b2 + init
//   bx 33..96  : l0 tile (BM=128, N=16) ; bx 97..224 : y rows
// ---------------------------------------------------------------------------
#define L0_AS  132   // [32][132]
#define L0_BS  17    // [32][17]
__global__ __launch_bounds__(256)
void prep_kernel(const float* __restrict__ Wq, const float* __restrict__ Wk,
                 const float* __restrict__ bq, const float* __restrict__ Wrel,
                 const float* __restrict__ h_grp,
                 const int* __restrict__ idx,
                 const int* __restrict__ src,
                 const int* __restrict__ dst) {
    __shared__ float sma[32 * L0_AS + 32 * L0_BS];   // 19 KB
    __shared__ int   sOff[2 * 128];
    const int tid = threadIdx.x;
    const int bx  = blockIdx.x;

    if (bx < 32) {
        float* s_wq = sma;              // [256][16]
        int k0 = bx * 16;
        #pragma unroll
        for (int r = 0; r < 16; r++) {
            int fid = tid + r * 256;
            int d = fid >> 4, kl = fid & 15;
            s_wq[d * 16 + kl] = __ldg(&Wq[(size_t)d * (2 * DH) + k0 + kl]);
        }
        __syncthreads();
        float acc[16] = {};
        int e = tid;
        #pragma unroll 4
        for (int d = 0; d < DH; d++) {
            float wkv = __ldg(&Wk[(size_t)d * DH + e]);
            #pragma unroll
            for (int kl = 0; kl < 16; kl++) acc[kl] += s_wq[d * 16 + kl] * wkv;
        }
        #pragma unroll
        for (int kl = 0; kl < 16; kl++)
            g_w2[(size_t)(k0 + kl) * DH + e] = acc[kl];
        return;
    }
    if (bx == 32) {
        float b2 = 0.f;
        for (int d = 0; d < DH; d++)
            b2 += __ldg(&bq[d]) * __ldg(&Wk[(size_t)d * DH + tid]);
        g_b2[tid] = b2;
        g_em[tid] = 0x7fffffff;
        g_em[tid + 256] = 0x7fffffff;
        if (tid == 0) g_acc_cnt = 0;
        return;
    }
    if (bx >= 97) {
        float* wx = sma;   // [16][65]
        #pragma unroll
        for (int r = 0; r < 4; r++) {
            int v = tid + r * 256;
            int t = v >> 6, j = v & 63;
            wx[t * 65 + j] = __ldg(&Wrel[(size_t)t * (2 * DH + DX) + 2 * DH + j]);
        }
        __syncthreads();
        int row = (bx - 97) * 256 + tid;
        const float4* x4 = reinterpret_cast<const float4*>(g_xsum + (size_t)row * DX);
        float acc[NTYP] = {};
        #pragma unroll
        for (int j4 = 0; j4 < 16; j4++) {
            float4 x = x4[j4];
            int j = j4 * 4;
            #pragma unroll
            for (int t = 0; t < NTYP; t++)
                acc[t] += x.x * wx[t * 65 + j]     + x.y * wx[t * 65 + j + 1]
                        + x.z * wx[t * 65 + j + 2] + x.w * wx[t * 65 + j + 3];
        }
        float4* yo = reinterpret_cast<float4*>(g_y + (size_t)row * NTYP);
        #pragma unroll
        for (int t4 = 0; t4 < 4; t4++)
            yo[t4] = make_float4(acc[t4 * 4], acc[t4 * 4 + 1], acc[t4 * 4 + 2], acc[t4 * 4 + 3]);
        return;
    }

    // ---- l0 tile: BM=128, N=16 ----
    float* As = sma;                 // [32][L0_AS]
    float* Bs = sma + 32 * L0_AS;    // [32][L0_BS]
    const int row0 = (bx - 33) * 128;

    if (tid < 128) {
        int q = row0 + tid;
        int i = __ldg(&idx[q]);
        sOff[tid]       = (i * LL + __ldg(&src[q])) * DH;
        sOff[128 + tid] = (i * LL + __ldg(&dst[q])) * DH;
    }
    __syncthreads();

    const int ty = tid >> 4;
    const int tx = tid & 15;
    float acc[8] = {};
    const int amr = tid >> 3;
    const int ac4 = (tid & 7) * 4;

    for (int ch = 0; ch < 16; ch++) {
        int kb = ch * 32;
        const int* off = sOff + ((kb >> 8) << 7);
        int kbl = kb & 255;
        float4 rA[4];
        #pragma unroll
        for (int j = 0; j < 4; j++)
            rA[j] = *reinterpret_cast<const float4*>(h_grp + off[amr + 32 * j] + kbl + ac4);
        float rb0 = __ldg(&Wrel[(size_t)(tid & 15) * (2 * DH + DX) + kb + (tid >> 4)]);
        float rb1 = __ldg(&Wrel[(size_t)(tid & 15) * (2 * DH + DX) + kb + (tid >> 4) + 16]);
        __syncthreads();
        #pragma unroll
        for (int j = 0; j < 4; j++) {
            int r = amr + 32 * j;
            As[(ac4 + 0) * L0_AS + r] = rA[j].x;
            As[(ac4 + 1) * L0_AS + r] = rA[j].y;
            As[(ac4 + 2) * L0_AS + r] = rA[j].z;
            As[(ac4 + 3) * L0_AS + r] = rA[j].w;
        }
        Bs[(tid >> 4) * L0_BS + (tid & 15)]        = rb0;
        Bs[((tid >> 4) + 16) * L0_BS + (tid & 15)] = rb1;
        __syncthreads();

        #pragma unroll
        for (int k = 0; k < 32; k++) {
            float b = Bs[k * L0_BS + tx];
            const float* ar = As + k * L0_AS + ty * 8;
            #pragma unroll
            for (int i = 0; i < 8; i++) acc[i] += ar[i] * b;
        }
    }
    #pragma unroll
    for (int i = 0; i < 8; i++) {
        int q = row0 + ty * 8 + i;
        g_l0[(size_t)q * NTYP + tx] = acc[i];
    }
}

// ---------------------------------------------------------------------------
// Kernel 3: TF32 gather-GEMM via cp.async: wv = q_in @ W2 + b2
// BM=64, BN=128, BK=32, 256 threads (warps 2Mx4N), grid (2,128).
// ---------------------------------------------------------------------------
#define AS_STRIDE 36
#define BS_STRIDE 136
#define GEMM_SMEM_FLOATS (2 * 64 * AS_STRIDE + 2 * 32 * BS_STRIDE + 128)
#define GEMM_SMEM_BYTES  (GEMM_SMEM_FLOATS * 4)

#define CP16(dst_u32, src_ptr) \
    asm volatile("cp.async.ca.shared.global [%0], [%1], 16;" :: "r"(dst_u32), "l"(src_ptr))
#define CP_COMMIT() asm volatile("cp.async.commit_group;")
#define CP_WAIT0()  asm volatile("cp.async.wait_group 0;")

__device__ __forceinline__ void mma_tf32(float* c, const uint32_t* a, const uint32_t* b) {
    asm volatile(
        "mma.sync.aligned.m16n8k8.row.col.f32.tf32.tf32.f32 "
        "{%0,%1,%2,%3}, {%4,%5,%6,%7}, {%8,%9}, {%0,%1,%2,%3};"
        : "+f"(c[0]), "+f"(c[1]), "+f"(c[2]), "+f"(c[3])
        : "r"(a[0]), "r"(a[1]), "r"(a[2]), "r"(a[3]), "r"(b[0]), "r"(b[1]));
}

__global__ __launch_bounds__(256, 3)
void gemm_tf32(const float* __restrict__ h_grp,
               const int* __restrict__ idx,
               const int* __restrict__ src,
               const int* __restrict__ dst) {
    extern __shared__ float dsm[];
    float* As = dsm;                                  // [2][64][AS_STRIDE]
    float* Bs = dsm + 2 * 64 * AS_STRIDE;             // [2][32][BS_STRIDE]
    int*  sOff = (int*)(Bs + 2 * 32 * BS_STRIDE);     // [2][64]

    const int tid  = threadIdx.x;
    const int lane = tid & 31;
    const int w    = tid >> 5;
    const int wm   = (w & 1) * 32;
    const int wn   = (w >> 1) * 32;
    const int row0 = blockIdx.y * 64;
    const int col0 = blockIdx.x * 128;

    if (tid < 64) {
        int q = row0 + tid;
        int i = __ldg(&idx[q]);
        sOff[tid]      = (i * LL + __ldg(&src[q])) * DH;
        sOff[64 + tid] = (i * LL + __ldg(&dst[q])) * DH;
    }
    __syncthreads();

    const int amr = tid >> 3;
    const int ac4 = (tid & 7) * 4;
    const int bkr = tid >> 5;
    const int bn4 = (tid & 31) * 4;

    int oA[2][2];
    oA[0][0] = sOff[amr];      oA[0][1] = sOff[amr + 32];
    oA[1][0] = sOff[64 + amr]; oA[1][1] = sOff[64 + amr + 32];

    const uint32_t as_u = (uint32_t)__cvta_generic_to_shared(As);
    const uint32_t bs_u = (uint32_t)__cvta_generic_to_shared(Bs);
    const uint32_t aDst = as_u + (uint32_t)((amr * AS_STRIDE + ac4) * 4);
    const uint32_t aDst2 = as_u + (uint32_t)(((amr + 32) * AS_STRIDE + ac4) * 4);
    const uint32_t bDst = bs_u + (uint32_t)((bkr * BS_STRIDE + bn4) * 4);

    auto cpChunk = [&](int ch) {
        int buf = ch & 1;
        int kb = ch * 32, kbl = kb & 255, h = kb >> 8;
        uint32_t ab = (uint32_t)(buf * (64 * AS_STRIDE * 4));
        CP16(aDst + ab,  h_grp + oA[h][0] + kbl + ac4);
        CP16(aDst2 + ab, h_grp + oA[h][1] + kbl + ac4);
        uint32_t bb = (uint32_t)(buf * (32 * BS_STRIDE * 4));
        #pragma unroll
        for (int j = 0; j < 4; j++)
            CP16(bDst + bb + (uint32_t)(8 * j * BS_STRIDE * 4),
                 g_w2 + (size_t)(kb + bkr + 8 * j) * DH + col0 + bn4);
        CP_COMMIT();
    };

    float acc[2][4][4] = {};
    cpChunk(0);
    CP_WAIT0();
    __syncthreads();

    for (int t = 0; t < 16; t++) {
        if (t < 15) cpChunk(t + 1);
        const int buf = t & 1;
        const float* a = As + buf * 64 * AS_STRIDE;
        const float* b = Bs + buf * 32 * BS_STRIDE;
        const int ar = wm + (lane >> 2);
        const int bn = wn + (lane >> 2);
        #pragma unroll
        for (int ks = 0; ks < 4; ks++) {
            int kc = ks * 8 + (lane & 3);
            uint32_t af[2][4], bf[4][2];
            #pragma unroll
            for (int mt = 0; mt < 2; mt++) {
                const float* ap = a + (ar + mt * 16) * AS_STRIDE + kc;
                af[mt][0] = __float_as_uint(ap[0]);
                af[mt][1] = __float_as_uint(ap[8 * AS_STRIDE]);
                af[mt][2] = __float_as_uint(ap[4]);
                af[mt][3] = __float_as_uint(ap[8 * AS_STRIDE + 4]);
            }
            #pragma unroll
            for (int nt = 0; nt < 4; nt++) {
                const float* bp = b + kc * BS_STRIDE + bn + nt * 8;
                bf[nt][0] = __float_as_uint(bp[0]);
                bf[nt][1] = __float_as_uint(bp[4 * BS_STRIDE]);
            }
            #pragma unroll
            for (int mt = 0; mt < 2; mt++)
                #pragma unroll
                for (int nt = 0; nt < 4; nt++)
                    mma_tf32(acc[mt][nt], af[mt], bf[nt]);
        }
        if (t < 15) {
            CP_WAIT0();
            __syncthreads();
        }
    }

    #pragma unroll
    for (int mt = 0; mt < 2; mt++) {
        int r = row0 + wm + mt * 16 + (lane >> 2);
        #pragma unroll
        for (int nt = 0; nt < 4; nt++) {
            int cb = col0 + wn + nt * 8 + (lane & 3) * 2;
            float b0 = __ldg(&g_b2[cb]);
            float b1 = __ldg(&g_b2[cb + 1]);
            *reinterpret_cast<float2*>(&g_wv[(size_t)r * DH + cb]) =
                make_float2(acc[mt][nt][0] + b0, acc[mt][nt][1] + b1);
            *reinterpret_cast<float2*>(&g_wv[(size_t)(r + 8) * DH + cb]) =
                make_float2(acc[mt][nt][2] + b0, acc[mt][nt][3] + b1);
        }
    }
}

// ---------------------------------------------------------------------------
// Kernel 4 (ncu slot): block-per-group attention, 768 threads / 24 warps,
// ONE query per warp, smem-broadcast wv (r11 instruction mix).
// smem 101 KB -> 2 blocks/SM = 48 warps (75% occ).
// ---------------------------------------------------------------------------
__device__ __forceinline__ int lbound(const int* __restrict__ a, int n, int key) {
    int lo = 0, hi = n;
    while (lo < hi) { int m = (lo + hi) >> 1; if (__ldg(&a[m]) < key) lo = m + 1; else hi = m; }
    return lo;
}

#define ATTN_WARPS   24
#define ATTN_THREADS 768
#define ATTN_SMEM_FLOATS (16384 + ATTN_WARPS * 256 + ATTN_WARPS * 64 + 1024 + 64 + 64 + 48)
#define ATTN_SMEM_BYTES  (ATTN_SMEM_FLOATS * 4)

__global__ __launch_bounds__(ATTN_THREADS, 2)
void attn_kernel(const float* __restrict__ h_grp,
                 const float* __restrict__ brel,
                 const int*   __restrict__ idx,
                 const int*   __restrict__ pos2grp,
                 const int*   __restrict__ msk,
                 const int*   __restrict__ typ,
                 float* __restrict__ out_logit) {
    extern __shared__ float sm[];
    float* s_ht  = sm;                          // 16384 : transposed h, [e][l]
    float* s_wvb = s_ht  + 16384;               // 24*256 : per-warp wv
    float* s_ab  = s_wvb + ATTN_WARPS * 256;    // 24*64  : per-warp a
    float* s_y   = s_ab  + ATTN_WARPS * 64;     // 1024  : y [l][16]
    float* s_msk = s_y   + 1024;                // 64
    int*   s_g   = (int*)(s_msk + 64);          // 64
    int*   s_acc = s_g + 64;                    // 24
    int*   s_em  = s_acc + 24;                  // 24

    const int n    = blockIdx.x;
    const int tid  = threadIdx.x;     // 768
    const int lane = tid & 31;
    const int w    = tid >> 5;        // 24 warps

    const int lo = lbound(idx, QQ, n);
    const int hi = lbound(idx, QQ, n + 1);
    if (lo >= hi) return;

    const int tt = lane & 15;
    float* wvp = s_wvb + w * 256;
    float* abp = s_ab  + w * 64;

    // ---- prefetch first pass's wv/l0/typ (latency hidden behind h staging) ----
    int q = lo + w;
    float l0v = 0.f;
    int   tyv = 0;
    if (q < hi) {
        const float4* wvA = reinterpret_cast<const float4*>(g_wv + (size_t)q * DH);
        float4* wvp4 = reinterpret_cast<float4*>(wvp);
        wvp4[lane]      = __ldg(wvA + lane);
        wvp4[32 + lane] = __ldg(wvA + 32 + lane);
        l0v = __ldg(&g_l0[(size_t)q * NTYP + tt]);
        tyv = __ldg(&typ[q * NTYP + tt]);
    }

    // ---- stage h transposed (conflict-free STS), 768 threads ----
    {
        const float4* hb4 = reinterpret_cast<const float4*>(h_grp + (size_t)n * LL * DH);
        for (int v = tid; v < 4096; v += ATTN_THREADS) {
            int l = v & 63, e4 = v >> 6;
            float4 hv = __ldg(hb4 + l * 64 + e4);
            int e = e4 * 4;
            s_ht[(e + 0) * 64 + l] = hv.x;
            s_ht[(e + 1) * 64 + l] = hv.y;
            s_ht[(e + 2) * 64 + l] = hv.z;
            s_ht[(e + 3) * 64 + l] = hv.w;
        }
    }
    if (tid < LL) {
        s_g[tid]   = __ldg(&pos2grp[n * LL + tid]);
        s_msk[tid] = (__ldg(&msk[n * LL + tid]) == 0) ? -INFINITY : 0.f;
    }
    __syncthreads();

    // gather y rows (64 x 16)
    for (int v = tid; v < 1024; v += ATTN_THREADS) {
        int l = v >> 4, t = v & 15;
        s_y[l * 16 + t] = __ldg(&g_y[(size_t)s_g[l] * NTYP + t]);
    }
    __syncthreads();

    int accW = 0, emW = 1;
    const float2* ht2 = reinterpret_cast<const float2*>(s_ht);
    const float mk0 = s_msk[2 * lane];
    const float mk1 = s_msk[2 * lane + 1];
    const float brl = __ldg(&brel[tt]);

    while (q < hi) {
        __syncwarp();   // wv staged (by this warp) -> visible

        // ---- scores for rows 2*lane, 2*lane+1 (4 FMA chains, smem broadcast) ----
        float p0a = 0.f, p0b = 0.f, p1a = 0.f, p1b = 0.f;
        #pragma unroll 4
        for (int e = 0; e < DH; e += 2) {
            float wva = wvp[e], wvb = wvp[e + 1];
            float2 ha = ht2[e * 32 + lane];
            float2 hb = ht2[(e + 1) * 32 + lane];
            p0a += ha.x * wva; p1a += ha.y * wva;
            p0b += hb.x * wvb; p1b += hb.y * wvb;
        }
        float v0 = (p0a + p0b) * 0.0625f + mk0;
        float v1 = (p1a + p1b) * 0.0625f + mk1;

        // ---- warp softmax over 64 ----
        float mmx = fmaxf(v0, v1);
        #pragma unroll
        for (int o = 16; o > 0; o >>= 1) mmx = fmaxf(mmx, __shfl_xor_sync(0xffffffffu, mmx, o));
        float e0 = __expf(v0 - mmx), e1 = __expf(v1 - mmx);
        float ssum = e0 + e1;
        #pragma unroll
        for (int o = 16; o > 0; o >>= 1) ssum += __shfl_xor_sync(0xffffffffu, ssum, o);
        float inv = 1.f / ssum;
        reinterpret_cast<float2*>(abp)[lane] = make_float2(e0 * inv, e1 * inv);
        __syncwarp();

        // ---- logit: lanes 0-15 and 16-31 duplicate over tt ----
        float pa = 0.f, pb = 0.f;
        #pragma unroll 8
        for (int l = 0; l < LL; l += 2) {
            pa += abp[l]     * s_y[l * 16 + tt];
            pb += abp[l + 1] * s_y[(l + 1) * 16 + tt];
        }
        float logit = pa + pb + l0v + brl;
        if (lane < 16) out_logit[(size_t)q * NTYP + tt] = logit;

        int gt = (logit > 0.f) ? 1 : 0;
        int ty = (tyv > 0) ? 1 : 0;
        unsigned m = __ballot_sync(0xffffffffu, gt == ty) & 0xFFFFu;
        if (lane == 0) {
            accW += __popc(m);
            emW &= (m == 0xFFFFu) ? 1 : 0;
        }

        // ---- next pass (rare: avg nq=16 <= 24 warps) ----
        q += ATTN_WARPS;
        if (q < hi) {
            const float4* wvA = reinterpret_cast<const float4*>(g_wv + (size_t)q * DH);
            float4* wvp4 = reinterpret_cast<float4*>(wvp);
            wvp4[lane]      = __ldg(wvA + lane);
            wvp4[32 + lane] = __ldg(wvA + 32 + lane);
            l0v = __ldg(&g_l0[(size_t)q * NTYP + tt]);
            tyv = __ldg(&typ[q * NTYP + tt]);
        }
    }

    if (lane == 0) { s_acc[w] = accW; s_em[w] = emW; }
    __syncthreads();
    if (tid == 0) {
        int a = 0, e = 1;
        #pragma unroll
        for (int r = 0; r < ATTN_WARPS; r++) { a += s_acc[r]; e &= s_em[r]; }
        atomicAdd(&g_acc_cnt, a);
        g_em[n] = e;
    }
}

// ---------------------------------------------------------------------------
// Kernel 5: finalize. out layout: [logit(131072), acc, emr, em(512)]
// ---------------------------------------------------------------------------
__global__ __launch_bounds__(512)
void finalize_kernel(float* __restrict__ out) {
    __shared__ float s_red[16];
    int tid = threadIdx.x;
    int lane = tid & 31, w = tid >> 5;
    float e = (float)g_em[tid];
    out[QQ * NTYP + 2 + tid] = e;
    float p = e;
    #pragma unroll
    for (int o = 16; o > 0; o >>= 1) p += __shfl_xor_sync(0xffffffffu, p, o);
    if (lane == 0) s_red[w] = p;
    __syncthreads();
    if (tid == 0) {
        float sum = 0.f;
        #pragma unroll
        for (int r = 0; r < 16; r++) sum += s_red[r];
        out[QQ * NTYP + 0] = (float)g_acc_cnt / (float)(QQ * NTYP);
        out[QQ * NTYP + 1] = sum / (float)NN;
    }
}

// ---------------------------------------------------------------------------
extern "C" void kernel_launch(void* const* d_in, const int* in_sizes, int n_in,
                              void* d_out, int out_size) {
    const float* h_grp   = (const float*)d_in[0];
    const float* tok_emb = (const float*)d_in[1];
    const float* Wq      = (const float*)d_in[2];
    const float* bq      = (const float*)d_in[3];
    const float* Wk      = (const float*)d_in[4];
    const float* Wrel    = (const float*)d_in[6];
    const float* brel    = (const float*)d_in[7];
    const int*   mem     = (const int*)d_in[8];
    const int*   grp     = (const int*)d_in[9];
    const int*   pos2grp = (const int*)d_in[10];
    const int*   msk     = (const int*)d_in[11];
    const int*   idx     = (const int*)d_in[12];
    const int*   src     = (const int*)d_in[13];
    const int*   dst     = (const int*)d_in[14];
    const int*   typ     = (const int*)d_in[15];
    float* out = (float*)d_out;

    float* xsum_ptr; cudaGetSymbolAddress((void**)&xsum_ptr, g_xsum);

    // memset node (not a kernel launch)
    cudaMemsetAsync(xsum_ptr, 0, (size_t)NSEG * DX * sizeof(float));

    // kernel #1: segment-sum scatter
    scatter_kernel<<<SC_NT / 256, 256>>>(tok_emb, mem, grp);

    // kernel #2: prep (W2 + b2/init + l0 + y)
    prep_kernel<<<225, 256>>>(Wq, Wk, bq, Wrel, h_grp, idx, src, dst);

    // kernel #3: TF32 gather-GEMM wv (cp.async pipeline)
    {
        cudaFuncSetAttribute(gemm_tf32, cudaFuncAttributeMaxDynamicSharedMemorySize, GEMM_SMEM_BYTES);
        dim3 grid(DH / 128, QQ / 64);
        gemm_tf32<<<grid, 256, GEMM_SMEM_BYTES>>>(h_grp, idx, src, dst);
    }

    // kernel #4 (ncu slot): attention + logits + metrics (768 threads, 1 q/warp)
    cudaFuncSetAttribute(attn_kernel, cudaFuncAttributeMaxDynamicSharedMemorySize, ATTN_SMEM_BYTES);
    attn_kernel<<<NN, ATTN_THREADS, ATTN_SMEM_BYTES>>>(h_grp, brel, idx, pos2grp, msk, typ, out);

    // kernel #5: finalize
    finalize_kernel<<<1, 512>>>(out);
}

// round 16
// speedup vs baseline: 1.1960x; 1.1191x over previous
#include <cuda_runtime.h>
#include <cuda_bf16.h>
#include <math.h>
#include <stdint.h>

// Problem constants
#define NN   512
#define LL   64
#define DH   256
#define DX   64
#define QQ   8192
#define NTYP 16
#define NMEM 262144
#define NSEG (NN*LL)        // 32768

// Scratch (device globals; no allocation allowed)
__device__ __align__(16) float g_xsum[NSEG * DX];       // 8 MB
__device__ __align__(16) float g_wv  [QQ * DH];         // 8 MB
__device__ __align__(16) float g_w2  [2 * DH * DH];     // 512x256
__device__ __align__(16) float g_y   [NSEG * NTYP];     // 2 MB
__device__ __align__(16) float g_l0  [QQ * NTYP];       // 512 KB
__device__ float g_b2  [DH];
__device__ int   g_em  [NN];
__device__ int   g_acc_cnt;

// ---------------------------------------------------------------------------
// Kernel 1: x_sum = segment_sum(tok_emb[mem], grp)  (MLP=4, v4 red)
// ---------------------------------------------------------------------------
#define SC_NT (NMEM * 16 / 4)   // 1,048,576 threads
__global__ __launch_bounds__(256)
void scatter_kernel(const float* __restrict__ tok_emb,
                    const int*   __restrict__ mem,
                    const int*   __restrict__ grp) {
    int t = blockIdx.x * 256 + threadIdx.x;
    int   gg[4], qd[4];
    float4 v[4];
    #pragma unroll
    for (int k = 0; k < 4; k++) {
        int task = t + k * SC_NT;
        int e = task >> 4;
        qd[k] = task & 15;
        int tok = __ldg(&mem[e]);
        gg[k]  = __ldg(&grp[e]);
        v[k] = __ldg(reinterpret_cast<const float4*>(tok_emb) + tok * 16 + qd[k]);
    }
    #pragma unroll
    for (int k = 0; k < 4; k++) {
        float* dst = &g_xsum[(size_t)gg[k] * DX + qd[k] * 4];
        asm volatile("red.global.add.v4.f32 [%0], {%1, %2, %3, %4};"
                     :: "l"(dst), "f"(v[k].x), "f"(v[k].y), "f"(v[k].z), "f"(v[k].w)
                     : "memory");
    }
}

// ---------------------------------------------------------------------------
// Kernel 2 (prep): grid 289 blocks, 256 threads. All fp32 paths.
//   bx 0..31    : W2 tile ; bx == 32 : b2 + init
//   bx 33..160  : l0 tile (BM=64, N=16): l0 = q_in @ Wrel_q^T
//   bx 161..288 : y rows : y[r,t] = x_sum[r,:] . Wrel[t,512:576]
// ---------------------------------------------------------------------------
#define L0A  65      // As stride [32][65] (rows as inner dim)
#define L0_BS 17     // [32][17]
// sized for the LARGEST path: W2 uses [256][16] = 4096 floats
#define PREP_SMEM_FLOATS (4096 + 32 * L0_BS + 128)
__global__ __launch_bounds__(256)
void prep_kernel(const float* __restrict__ Wq, const float* __restrict__ Wk,
                 const float* __restrict__ bq, const float* __restrict__ Wrel,
                 const float* __restrict__ h_grp,
                 const int* __restrict__ idx,
                 const int* __restrict__ src,
                 const int* __restrict__ dst) {
    __shared__ float sma[PREP_SMEM_FLOATS];   // ~18.7 KB
    __shared__ int   sOff[2 * 64];
    const int tid = threadIdx.x;
    const int bx  = blockIdx.x;

    if (bx < 32) {
        // ---- W2 tile ----
        float* s_wq = sma;              // [256][16] = 4096 floats
        int k0 = bx * 16;
        #pragma unroll
        for (int r = 0; r < 16; r++) {
            int fid = tid + r * 256;
            int d = fid >> 4, kl = fid & 15;
            s_wq[d * 16 + kl] = __ldg(&Wq[(size_t)d * (2 * DH) + k0 + kl]);
        }
        __syncthreads();
        float acc[16] = {};
        int e = tid;
        #pragma unroll 4
        for (int d = 0; d < DH; d++) {
            float wkv = __ldg(&Wk[(size_t)d * DH + e]);
            #pragma unroll
            for (int kl = 0; kl < 16; kl++) acc[kl] += s_wq[d * 16 + kl] * wkv;
        }
        #pragma unroll
        for (int kl = 0; kl < 16; kl++)
            g_w2[(size_t)(k0 + kl) * DH + e] = acc[kl];
        return;
    }
    if (bx == 32) {
        float b2 = 0.f;
        for (int d = 0; d < DH; d++)
            b2 += __ldg(&bq[d]) * __ldg(&Wk[(size_t)d * DH + tid]);
        g_b2[tid] = b2;
        g_em[tid] = 0x7fffffff;
        g_em[tid + 256] = 0x7fffffff;
        if (tid == 0) g_acc_cnt = 0;
        return;
    }
    if (bx >= 161) {
        // ---- y path ----
        float* wx = sma;   // [16][65] = 1040 floats
        #pragma unroll
        for (int r = 0; r < 4; r++) {
            int v = tid + r * 256;
            int t = v >> 6, j = v & 63;
            wx[t * 65 + j] = __ldg(&Wrel[(size_t)t * (2 * DH + DX) + 2 * DH + j]);
        }
        __syncthreads();
        int row = (bx - 161) * 256 + tid;
        const float4* x4 = reinterpret_cast<const float4*>(g_xsum + (size_t)row * DX);
        float acc[NTYP] = {};
        #pragma unroll
        for (int j4 = 0; j4 < 16; j4++) {
            float4 x = x4[j4];
            int j = j4 * 4;
            #pragma unroll
            for (int t = 0; t < NTYP; t++)
                acc[t] += x.x * wx[t * 65 + j]     + x.y * wx[t * 65 + j + 1]
                        + x.z * wx[t * 65 + j + 2] + x.w * wx[t * 65 + j + 3];
        }
        float4* yo = reinterpret_cast<float4*>(g_y + (size_t)row * NTYP);
        #pragma unroll
        for (int t4 = 0; t4 < 4; t4++)
            yo[t4] = make_float4(acc[t4 * 4], acc[t4 * 4 + 1], acc[t4 * 4 + 2], acc[t4 * 4 + 3]);
        return;
    }

    // ---- l0 tile: BM=64, N=16 ----  (128 blocks: bx 33..160)
    float* As = sma;                 // [32][L0A] = 2080 floats, As[k][row]
    float* Bs = sma + 32 * L0A;      // [32][L0_BS] = 544 floats
    const int row0 = (bx - 33) * 64;

    if (tid < 64) {
        int q = row0 + tid;
        int i = __ldg(&idx[q]);
        sOff[tid]      = (i * LL + __ldg(&src[q])) * DH;
        sOff[64 + tid] = (i * LL + __ldg(&dst[q])) * DH;
    }
    __syncthreads();

    const int ty = tid >> 4;        // 0..15 -> 4 rows each
    const int tx = tid & 15;        // type
    float acc[4] = {};
    const int amr = tid >> 2;       // row 0..63
    const int ac8 = (tid & 3) * 8;  // col base: two float4 at ac8, ac8+4

    for (int ch = 0; ch < 16; ch++) {
        int kb = ch * 32;
        const int* off = sOff + ((kb >> 8) << 6);
        int kbl = kb & 255;
        float4 rA0 = *reinterpret_cast<const float4*>(h_grp + off[amr] + kbl + ac8);
        float4 rA1 = *reinterpret_cast<const float4*>(h_grp + off[amr] + kbl + ac8 + 4);
        float rb0 = __ldg(&Wrel[(size_t)(tid & 15) * (2 * DH + DX) + kb + (tid >> 4)]);
        float rb1 = __ldg(&Wrel[(size_t)(tid & 15) * (2 * DH + DX) + kb + (tid >> 4) + 16]);
        __syncthreads();   // protect previous iteration's reads
        As[(ac8 + 0) * L0A + amr] = rA0.x;
        As[(ac8 + 1) * L0A + amr] = rA0.y;
        As[(ac8 + 2) * L0A + amr] = rA0.z;
        As[(ac8 + 3) * L0A + amr] = rA0.w;
        As[(ac8 + 4) * L0A + amr] = rA1.x;
        As[(ac8 + 5) * L0A + amr] = rA1.y;
        As[(ac8 + 6) * L0A + amr] = rA1.z;
        As[(ac8 + 7) * L0A + amr] = rA1.w;
        Bs[(tid >> 4) * L0_BS + (tid & 15)]        = rb0;
        Bs[((tid >> 4) + 16) * L0_BS + (tid & 15)] = rb1;
        __syncthreads();

        #pragma unroll
        for (int k = 0; k < 32; k++) {
            float b = Bs[k * L0_BS + tx];
            const float* ar = As + k * L0A + ty * 4;
            #pragma unroll
            for (int i = 0; i < 4; i++) acc[i] += ar[i] * b;
        }
    }
    #pragma unroll
    for (int i = 0; i < 4; i++) {
        int q = row0 + ty * 4 + i;
        g_l0[(size_t)q * NTYP + tx] = acc[i];
    }
}

// ---------------------------------------------------------------------------
// Kernel 3: TF32 gather-GEMM via cp.async: wv = q_in @ W2 + b2
// BM=64, BN=128, BK=32, 256 threads (warps 2Mx4N), grid (2,128).
// ---------------------------------------------------------------------------
#define AS_STRIDE 36
#define BS_STRIDE 136
#define GEMM_SMEM_FLOATS (2 * 64 * AS_STRIDE + 2 * 32 * BS_STRIDE + 128)
#define GEMM_SMEM_BYTES  (GEMM_SMEM_FLOATS * 4)

#define CP16(dst_u32, src_ptr) \
    asm volatile("cp.async.ca.shared.global [%0], [%1], 16;" :: "r"(dst_u32), "l"(src_ptr))
#define CP_COMMIT() asm volatile("cp.async.commit_group;")
#define CP_WAIT0()  asm volatile("cp.async.wait_group 0;")

__device__ __forceinline__ void mma_tf32(float* c, const uint32_t* a, const uint32_t* b) {
    asm volatile(
        "mma.sync.aligned.m16n8k8.row.col.f32.tf32.tf32.f32 "
        "{%0,%1,%2,%3}, {%4,%5,%6,%7}, {%8,%9}, {%0,%1,%2,%3};"
        : "+f"(c[0]), "+f"(c[1]), "+f"(c[2]), "+f"(c[3])
        : "r"(a[0]), "r"(a[1]), "r"(a[2]), "r"(a[3]), "r"(b[0]), "r"(b[1]));
}

__global__ __launch_bounds__(256, 3)
void gemm_tf32(const float* __restrict__ h_grp,
               const int* __restrict__ idx,
               const int* __restrict__ src,
               const int* __restrict__ dst) {
    extern __shared__ float dsm[];
    float* As = dsm;                                  // [2][64][AS_STRIDE]
    float* Bs = dsm + 2 * 64 * AS_STRIDE;             // [2][32][BS_STRIDE]
    int*  sOff = (int*)(Bs + 2 * 32 * BS_STRIDE);     // [2][64]

    const int tid  = threadIdx.x;
    const int lane = tid & 31;
    const int w    = tid >> 5;
    const int wm   = (w & 1) * 32;
    const int wn   = (w >> 1) * 32;
    const int row0 = blockIdx.y * 64;
    const int col0 = blockIdx.x * 128;

    if (tid < 64) {
        int q = row0 + tid;
        int i = __ldg(&idx[q]);
        sOff[tid]      = (i * LL + __ldg(&src[q])) * DH;
        sOff[64 + tid] = (i * LL + __ldg(&dst[q])) * DH;
    }
    __syncthreads();

    const int amr = tid >> 3;
    const int ac4 = (tid & 7) * 4;
    const int bkr = tid >> 5;
    const int bn4 = (tid & 31) * 4;

    int oA[2][2];
    oA[0][0] = sOff[amr];      oA[0][1] = sOff[amr + 32];
    oA[1][0] = sOff[64 + amr]; oA[1][1] = sOff[64 + amr + 32];

    const uint32_t as_u = (uint32_t)__cvta_generic_to_shared(As);
    const uint32_t bs_u = (uint32_t)__cvta_generic_to_shared(Bs);
    const uint32_t aDst = as_u + (uint32_t)((amr * AS_STRIDE + ac4) * 4);
    const uint32_t aDst2 = as_u + (uint32_t)(((amr + 32) * AS_STRIDE + ac4) * 4);
    const uint32_t bDst = bs_u + (uint32_t)((bkr * BS_STRIDE + bn4) * 4);

    auto cpChunk = [&](int ch) {
        int buf = ch & 1;
        int kb = ch * 32, kbl = kb & 255, h = kb >> 8;
        uint32_t ab = (uint32_t)(buf * (64 * AS_STRIDE * 4));
        CP16(aDst + ab,  h_grp + oA[h][0] + kbl + ac4);
        CP16(aDst2 + ab, h_grp + oA[h][1] + kbl + ac4);
        uint32_t bb = (uint32_t)(buf * (32 * BS_STRIDE * 4));
        #pragma unroll
        for (int j = 0; j < 4; j++)
            CP16(bDst + bb + (uint32_t)(8 * j * BS_STRIDE * 4),
                 g_w2 + (size_t)(kb + bkr + 8 * j) * DH + col0 + bn4);
        CP_COMMIT();
    };

    float acc[2][4][4] = {};
    cpChunk(0);
    CP_WAIT0();
    __syncthreads();

    for (int t = 0; t < 16; t++) {
        if (t < 15) cpChunk(t + 1);
        const int buf = t & 1;
        const float* a = As + buf * 64 * AS_STRIDE;
        const float* b = Bs + buf * 32 * BS_STRIDE;
        const int ar = wm + (lane >> 2);
        const int bn = wn + (lane >> 2);
        #pragma unroll
        for (int ks = 0; ks < 4; ks++) {
            int kc = ks * 8 + (lane & 3);
            uint32_t af[2][4], bf[4][2];
            #pragma unroll
            for (int mt = 0; mt < 2; mt++) {
                const float* ap = a + (ar + mt * 16) * AS_STRIDE + kc;
                af[mt][0] = __float_as_uint(ap[0]);
                af[mt][1] = __float_as_uint(ap[8 * AS_STRIDE]);
                af[mt][2] = __float_as_uint(ap[4]);
                af[mt][3] = __float_as_uint(ap[8 * AS_STRIDE + 4]);
            }
            #pragma unroll
            for (int nt = 0; nt < 4; nt++) {
                const float* bp = b + kc * BS_STRIDE + bn + nt * 8;
                bf[nt][0] = __float_as_uint(bp[0]);
                bf[nt][1] = __float_as_uint(bp[4 * BS_STRIDE]);
            }
            #pragma unroll
            for (int mt = 0; mt < 2; mt++)
                #pragma unroll
                for (int nt = 0; nt < 4; nt++)
                    mma_tf32(acc[mt][nt], af[mt], bf[nt]);
        }
        if (t < 15) {
            CP_WAIT0();
            __syncthreads();
        }
    }

    #pragma unroll
    for (int mt = 0; mt < 2; mt++) {
        int r = row0 + wm + mt * 16 + (lane >> 2);
        #pragma unroll
        for (int nt = 0; nt < 4; nt++) {
            int cb = col0 + wn + nt * 8 + (lane & 3) * 2;
            float b0 = __ldg(&g_b2[cb]);
            float b1 = __ldg(&g_b2[cb + 1]);
            *reinterpret_cast<float2*>(&g_wv[(size_t)r * DH + cb]) =
                make_float2(acc[mt][nt][0] + b0, acc[mt][nt][1] + b1);
            *reinterpret_cast<float2*>(&g_wv[(size_t)(r + 8) * DH + cb]) =
                make_float2(acc[mt][nt][2] + b0, acc[mt][nt][3] + b1);
        }
    }
}

// ---------------------------------------------------------------------------
// Kernel 4 (ncu slot): block-per-group attention (r11 version, fp32),
// 512 threads / 16 warps, TWO queries per warp, first-pass wv prefetch.
// ---------------------------------------------------------------------------
__device__ __forceinline__ int lbound(const int* __restrict__ a, int n, int key) {
    int lo = 0, hi = n;
    while (lo < hi) { int m = (lo + hi) >> 1; if (__ldg(&a[m]) < key) lo = m + 1; else hi = m; }
    return lo;
}

#define ATTN_WARPS 16
#define ATTN_SMEM_FLOATS (16384 + ATTN_WARPS * 512 + ATTN_WARPS * 128 + 1024 + 64 + 64 + 32)
#define ATTN_SMEM_BYTES  (ATTN_SMEM_FLOATS * 4)

__global__ __launch_bounds__(512)
void attn_kernel(const float* __restrict__ h_grp,
                 const float* __restrict__ brel,
                 const int*   __restrict__ idx,
                 const int*   __restrict__ pos2grp,
                 const int*   __restrict__ msk,
                 const int*   __restrict__ typ,
                 float* __restrict__ out_logit) {
    extern __shared__ float sm[];
    float* s_ht  = sm;                          // 16384 : transposed h, [e][l]
    float* s_wvb = s_ht  + 16384;               // 16*512 : per-warp wv x2
    float* s_ab  = s_wvb + ATTN_WARPS * 512;    // 16*128 : per-warp a x2
    float* s_y   = s_ab  + ATTN_WARPS * 128;    // 1024  : y [l][16]
    float* s_msk = s_y   + 1024;                // 64
    int*   s_g   = (int*)(s_msk + 64);          // 64
    int*   s_acc = s_g + 64;                    // 16
    int*   s_em  = s_acc + 16;                  // 16

    const int n    = blockIdx.x;
    const int tid  = threadIdx.x;     // 512
    const int lane = tid & 31;
    const int w    = tid >> 5;        // 16 warps

    const int lo = lbound(idx, QQ, n);
    const int hi = lbound(idx, QQ, n + 1);
    if (lo >= hi) return;

    float* wvp = s_wvb + w * 512;     // [0..255]=A, [256..511]=B
    float* abp = s_ab  + w * 128;     // [0..63]=A, [64..127]=B

    // ---- prefetch first pass's wv (latency hidden behind h staging) ----
    int qb = lo + 2 * w;
    if (qb < hi) {
        const int qB = (qb + 1 < hi) ? qb + 1 : qb;
        const float4* wvA = reinterpret_cast<const float4*>(g_wv + (size_t)qb * DH);
        const float4* wvB = reinterpret_cast<const float4*>(g_wv + (size_t)qB * DH);
        float4* wvp4 = reinterpret_cast<float4*>(wvp);
        wvp4[lane]      = __ldg(wvA + lane);
        wvp4[32 + lane] = __ldg(wvA + 32 + lane);
        wvp4[64 + lane] = __ldg(wvB + lane);
        wvp4[96 + lane] = __ldg(wvB + 32 + lane);
    }

    // stage h transposed (conflict-free STS), spread over 512 threads
    {
        const float4* hb4 = reinterpret_cast<const float4*>(h_grp + (size_t)n * LL * DH);
        #pragma unroll
        for (int k = 0; k < 8; k++) {
            int v = tid + k * 512;
            int l = v & 63, e4 = v >> 6;
            float4 hv = __ldg(hb4 + l * 64 + e4);
            int e = e4 * 4;
            s_ht[(e + 0) * 64 + l] = hv.x;
            s_ht[(e + 1) * 64 + l] = hv.y;
            s_ht[(e + 2) * 64 + l] = hv.z;
            s_ht[(e + 3) * 64 + l] = hv.w;
        }
    }
    if (tid < LL) {
        s_g[tid]   = __ldg(&pos2grp[n * LL + tid]);
        s_msk[tid] = (__ldg(&msk[n * LL + tid]) == 0) ? -INFINITY : 0.f;
    }
    __syncthreads();

    // gather y rows (64 x 16)
    #pragma unroll
    for (int k = 0; k < 2; k++) {
        int v = tid + k * 512;
        int l = v >> 4, t = v & 15;
        s_y[l * 16 + t] = __ldg(&g_y[(size_t)s_g[l] * NTYP + t]);
    }
    __syncthreads();

    int accW = 0, emW = 1;
    const float2* ht2 = reinterpret_cast<const float2*>(s_ht);
    const float mk0 = s_msk[2 * lane];
    const float mk1 = s_msk[2 * lane + 1];
    const int tt = lane & 15;
    const float brl = __ldg(&brel[tt]);

    while (qb < hi) {
        const int qA = qb;
        const bool hasB = (qb + 1 < hi);
        const int qB = hasB ? qb + 1 : qb;
        __syncwarp();   // wv staged by this warp -> visible

        // scores for rows 2*lane, 2*lane+1, both queries
        float a0 = 0.f, a1 = 0.f, b0 = 0.f, b1 = 0.f;
        #pragma unroll 8
        for (int e = 0; e < DH; e++) {
            float wa = wvp[e];
            float wb = wvp[256 + e];
            float2 h = ht2[e * 32 + lane];
            a0 += h.x * wa; a1 += h.y * wa;
            b0 += h.x * wb; b1 += h.y * wb;
        }
        float vA0 = a0 * 0.0625f + mk0, vA1 = a1 * 0.0625f + mk1;
        float vB0 = b0 * 0.0625f + mk0, vB1 = b1 * 0.0625f + mk1;

        // dual warp softmax over 64
        float mA = fmaxf(vA0, vA1), mB = fmaxf(vB0, vB1);
        #pragma unroll
        for (int o = 16; o > 0; o >>= 1) {
            mA = fmaxf(mA, __shfl_xor_sync(0xffffffffu, mA, o));
            mB = fmaxf(mB, __shfl_xor_sync(0xffffffffu, mB, o));
        }
        float eA0 = __expf(vA0 - mA), eA1 = __expf(vA1 - mA);
        float eB0 = __expf(vB0 - mB), eB1 = __expf(vB1 - mB);
        float sA = eA0 + eA1, sB = eB0 + eB1;
        #pragma unroll
        for (int o = 16; o > 0; o >>= 1) {
            sA += __shfl_xor_sync(0xffffffffu, sA, o);
            sB += __shfl_xor_sync(0xffffffffu, sB, o);
        }
        float iA = 1.f / sA, iB = 1.f / sB;
        reinterpret_cast<float2*>(abp)[lane]      = make_float2(eA0 * iA, eA1 * iA);
        reinterpret_cast<float2*>(abp + 64)[lane] = make_float2(eB0 * iB, eB1 * iB);
        __syncwarp();

        // logits: lanes 0-15 -> query A, lanes 16-31 -> query B
        const int   qSel = (lane < 16) ? qA : qB;
        const float* aSel = (lane < 16) ? abp : abp + 64;
        float pa = 0.f, pb = 0.f;
        #pragma unroll 8
        for (int l = 0; l < LL; l += 2) {
            pa += aSel[l]     * s_y[l * 16 + tt];
            pb += aSel[l + 1] * s_y[(l + 1) * 16 + tt];
        }
        float logit = pa + pb + __ldg(&g_l0[(size_t)qSel * NTYP + tt]) + brl;
        if (lane < 16 || hasB) out_logit[(size_t)qSel * NTYP + tt] = logit;

        int gt = (logit > 0.f) ? 1 : 0;
        int ty = (__ldg(&typ[qSel * NTYP + tt]) > 0) ? 1 : 0;
        unsigned m = __ballot_sync(0xffffffffu, gt == ty);
        if (lane == 0) {
            unsigned mAq = m & 0xFFFFu, mBq = m >> 16;
            accW += __popc(mAq);
            emW &= (mAq == 0xFFFFu) ? 1 : 0;
            if (hasB) {
                accW += __popc(mBq);
                emW &= (mBq == 0xFFFFu) ? 1 : 0;
            }
        }

        // next pass (rare): stage next wv
        qb += 2 * ATTN_WARPS;
        if (qb < hi) {
            const int qB2 = (qb + 1 < hi) ? qb + 1 : qb;
            const float4* wvA = reinterpret_cast<const float4*>(g_wv + (size_t)qb * DH);
            const float4* wvB = reinterpret_cast<const float4*>(g_wv + (size_t)qB2 * DH);
            float4* wvp4 = reinterpret_cast<float4*>(wvp);
            wvp4[lane]      = __ldg(wvA + lane);
            wvp4[32 + lane] = __ldg(wvA + 32 + lane);
            wvp4[64 + lane] = __ldg(wvB + lane);
            wvp4[96 + lane] = __ldg(wvB + 32 + lane);
        }
    }

    if (lane == 0) { s_acc[w] = accW; s_em[w] = emW; }
    __syncthreads();
    if (tid == 0) {
        int a = 0, e = 1;
        #pragma unroll
        for (int r = 0; r < ATTN_WARPS; r++) { a += s_acc[r]; e &= s_em[r]; }
        atomicAdd(&g_acc_cnt, a);
        g_em[n] = e;
    }
}

// ---------------------------------------------------------------------------
// Kernel 5: finalize. out layout: [logit(131072), acc, emr, em(512)]
// ---------------------------------------------------------------------------
__global__ __launch_bounds__(512)
void finalize_kernel(float* __restrict__ out) {
    __shared__ float s_red[16];
    int tid = threadIdx.x;
    int lane = tid & 31, w = tid >> 5;
    float e = (float)g_em[tid];
    out[QQ * NTYP + 2 + tid] = e;
    float p = e;
    #pragma unroll
    for (int o = 16; o > 0; o >>= 1) p += __shfl_xor_sync(0xffffffffu, p, o);
    if (lane == 0) s_red[w] = p;
    __syncthreads();
    if (tid == 0) {
        float sum = 0.f;
        #pragma unroll
        for (int r = 0; r < 16; r++) sum += s_red[r];
        out[QQ * NTYP + 0] = (float)g_acc_cnt / (float)(QQ * NTYP);
        out[QQ * NTYP + 1] = sum / (float)NN;
    }
}

// ---------------------------------------------------------------------------
extern "C" void kernel_launch(void* const* d_in, const int* in_sizes, int n_in,
                              void* d_out, int out_size) {
    const float* h_grp   = (const float*)d_in[0];
    const float* tok_emb = (const float*)d_in[1];
    const float* Wq      = (const float*)d_in[2];
    const float* bq      = (const float*)d_in[3];
    const float* Wk      = (const float*)d_in[4];
    const float* Wrel    = (const float*)d_in[6];
    const float* brel    = (const float*)d_in[7];
    const int*   mem     = (const int*)d_in[8];
    const int*   grp     = (const int*)d_in[9];
    const int*   pos2grp = (const int*)d_in[10];
    const int*   msk     = (const int*)d_in[11];
    const int*   idx     = (const int*)d_in[12];
    const int*   src     = (const int*)d_in[13];
    const int*   dst     = (const int*)d_in[14];
    const int*   typ     = (const int*)d_in[15];
    float* out = (float*)d_out;

    float* xsum_ptr; cudaGetSymbolAddress((void**)&xsum_ptr, g_xsum);

    // memset node (not a kernel launch)
    cudaMemsetAsync(xsum_ptr, 0, (size_t)NSEG * DX * sizeof(float));

    // kernel #1: segment-sum scatter
    scatter_kernel<<<SC_NT / 256, 256>>>(tok_emb, mem, grp);

    // kernel #2: prep (W2 + b2/init + l0[BM=64] + y)
    prep_kernel<<<289, 256>>>(Wq, Wk, bq, Wrel, h_grp, idx, src, dst);

    // kernel #3: TF32 gather-GEMM wv (cp.async pipeline)
    {
        cudaFuncSetAttribute(gemm_tf32, cudaFuncAttributeMaxDynamicSharedMemorySize, GEMM_SMEM_BYTES);
        dim3 grid(DH / 128, QQ / 64);
        gemm_tf32<<<grid, 256, GEMM_SMEM_BYTES>>>(h_grp, idx, src, dst);
    }

    // kernel #4 (ncu slot): attention + logits + metrics (r11 fp32, 2q/warp)
    cudaFuncSetAttribute(attn_kernel, cudaFuncAttributeMaxDynamicSharedMemorySize, ATTN_SMEM_BYTES);
    attn_kernel<<<NN, 512, ATTN_SMEM_BYTES>>>(h_grp, brel, idx, pos2grp, msk, typ, out);

    // kernel #5: finalize
    finalize_kernel<<<1, 512>>>(out);
}